// round 17
// baseline (speedup 1.0000x reference)
#include <cuda_runtime.h>

#define BN   8
#define CN   64
#define HN   256
#define WN   256
#define HP   257
#define WP   257
#define HWN  (HN * WN)          // 65536
#define NPIX (HP * WP)          // 66049
#define LN_EPS 1e-5f
#define NEG_SLOPE 0.01f

// Padded channel-sum plane: cs(h,w) at [(h+3)*CST + (w+4)]. 262 rows
// (cs rows -3..258), stride 268 (cols -4..263). Border stays zero
// (zero-initialized globals; interior-only writes). Composed 6x6 stencil
// taps (rows/cols -3..+2) never leave the plane.
#define CROWS 262
#define CST   268
#define CST4  (CST / 4)         // 67
#define CPLANE (CROWS * CST)

#define NBLK  65                // blocks per image (4 output rows each)
#define NGRID (NBLK * BN)       // 520 blocks, single resident wave
#define NTHR  256
#define Q4    (HWN / 4)         // 16384 float4 columns per image plane

#define CHW    8                // float4 columns per chansum chunk
#define NCHUNK (Q4 / CHW)       // 2048 chunks per image

// Scratch (static device globals — allowed)
__device__ float g_csp[BN * CPLANE];       // padded channel sum (~2.25 MB)
__device__ float g_part[BN * NBLK * 2];    // per-block (sum, sumsq)
__device__ unsigned int g_tkt[BN * 32];    // per-image barrier counters, 128B
                                           // apart; monotone +2*NBLK/launch
__device__ unsigned int g_q[BN * 32];      // per-image chansum work queues;
                                           // grab-with-restore nets exactly
                                           // +NCHUNK per launch (replay-safe:
                                           // tickets >= limit are restored and
                                           // never re-issued below limit)

// ---------------------------------------------------------------------------
// Per-image ticket barrier: only the 65 blocks of one image synchronize.
// Single resident wave (520 <= 4*148, launch_bounds(256,4)) => spin safe.
// ---------------------------------------------------------------------------
__device__ __forceinline__ void img_barrier(int tid, int b) {
    __syncthreads();
    if (tid == 0) {
        __threadfence();                              // publish this block's stores
        unsigned* c = &g_tkt[b * 32];
        unsigned t = atomicAdd(c, 1u) + 1u;
        unsigned target = ((t + NBLK - 1u) / NBLK) * NBLK;
        volatile unsigned* vc = c;
        while (*vc < target) __nanosleep(32);
    }
    __syncthreads();
    __threadfence();                                  // acquire peers' stores
}

// ---------------------------------------------------------------------------
// One persistent kernel: warp-stealing chansum (ticket prefetch, no block
// syncs) -> per-image barrier -> vertical 4-px 36-tap stencil (+ LN
// partials) -> per-image barrier -> stats + normalize + LeakyReLU.
// ---------------------------------------------------------------------------
__global__ void __launch_bounds__(NTHR, 4)
k_all(const float* __restrict__ x, const float* __restrict__ cw,
      const float* __restrict__ cb, float* __restrict__ out) {
    __shared__ float s_c6[36];                // composed 6x6 stencil coeffs
    __shared__ float s_tile[9 * CST];         // 9 padded rows (9.4 KB)
    __shared__ float s_red[8][2];
    __shared__ unsigned s_epoch;

    const int tid  = threadIdx.x;
    const int lane = tid & 31;
    const int blk  = blockIdx.x;
    const int b    = blk / NBLK;              // this block's image
    const int xb   = blk - b * NBLK;          // index within image [0,65)

    // ---- Epoch read (before any same-image g_tkt increment can occur:
    //      increments require a whole image-b block to finish phase 0, >>
    //      the sub-us scheduling skew of these reads) ----
    if (tid == 0) s_epoch = g_tkt[b * 32] / (2u * NBLK);

    // ---- Composed coefficients: pool(2) o 16-tap shift stencil = 6x6 ----
    if (tid < 36) {
        const signed char tdr[16] = {2,-2, 2,-2, 2,-2, 2,-2, 2,-2, 1,-1, 0,0, -1,1};
        const signed char tdc[16] = {2,-2, 1,-1, 0, 0,-1, 1,-2, 2,-2, 2,-2,2, -2,2};
        const signed char twi[16] = {0, 0, 1, 1, 2, 2, 3, 3, 4, 4, 5, 5, 6,6,  7,7};
        const signed char tsg[16] = {1,-1, 1,-1, 1,-1, 1,-1, 1,-1, 1,-1, 1,-1, 1,-1};
        int r = tid / 6 - 3, c = tid % 6 - 3;
        float acc = 0.f;
        for (int t2 = 0; t2 < 16; ++t2) {
            int ur = r - tdr[t2], uc = c - tdc[t2];
            if ((ur == 0 || ur == -1) && (uc == 0 || uc == -1))
                acc += (float)tsg[t2] * cw[twi[t2]];
        }
        s_c6[tid] = 0.25f * acc;
    }
    __syncthreads();

    // ---- Phase 0: chansum via per-image WARP work-stealing ----
    // Chunk = 8 float4 columns x 64 channels (32 KB). lane&7 = column,
    // lane>>3 = 16-channel group. Ticket prefetch hides atomic latency.
    {
        const unsigned qbase = s_epoch * NCHUNK;
        const unsigned limit = qbase + NCHUNK;
        unsigned* qc = &g_q[b * 32];
        const float4* xbase = reinterpret_cast<const float4*>(x)
                              + ((size_t)b * CN + (size_t)(lane >> 3) * 16) * Q4;
        float* plane0 = g_csp + (size_t)b * CPLANE;

        unsigned t;
        {   // initial grab
            unsigned g = 0;
            if (lane == 0) {
                g = atomicAdd(qc, 1u);
                if (g >= limit) { atomicSub(qc, 1u); g = 0xFFFFFFFFu; }
            }
            t = __shfl_sync(0xffffffffu, g, 0);
        }
        while (t != 0xFFFFFFFFu) {
            // prefetch next ticket (latency overlaps the loads below)
            unsigned g = 0;
            if (lane == 0) {
                g = atomicAdd(qc, 1u);
                if (g >= limit) { atomicSub(qc, 1u); g = 0xFFFFFFFFu; }
            }
            unsigned t_next = __shfl_sync(0xffffffffu, g, 0);

            int col = (int)(t - qbase) * CHW + (lane & 7);
            const float4* xp = xbase + col;
            float ax = 0.f, ay = 0.f, az = 0.f, aw = 0.f;
#pragma unroll
            for (int cc = 0; cc < 16; cc += 8) {
                float4 buf[8];
#pragma unroll
                for (int i = 0; i < 8; ++i)
                    buf[i] = __ldcs(xp + (size_t)(cc + i) * Q4);
#pragma unroll
                for (int i = 0; i < 8; ++i) {
                    ax += buf[i].x; ay += buf[i].y; az += buf[i].z; aw += buf[i].w;
                }
            }
            // combine channel groups: (g0+g2)+(g1+g3), fixed order
            ax += __shfl_down_sync(0xffffffffu, ax, 16);
            ay += __shfl_down_sync(0xffffffffu, ay, 16);
            az += __shfl_down_sync(0xffffffffu, az, 16);
            aw += __shfl_down_sync(0xffffffffu, aw, 16);
            ax += __shfl_down_sync(0xffffffffu, ax, 8);
            ay += __shfl_down_sync(0xffffffffu, ay, 8);
            az += __shfl_down_sync(0xffffffffu, az, 8);
            aw += __shfl_down_sync(0xffffffffu, aw, 8);
            if (lane < 8) {
                int p = col * 4;
                int h = p >> 8, w = p & 255;
                *reinterpret_cast<float4*>(plane0 + (h + 3) * CST + (w + 4)) =
                    make_float4(ax, ay, az, aw);
            }
            t = t_next;
        }
    }

    img_barrier(tid, b);                      // image b's cs plane ready

    // ---- Phase B: vertical 4-pixel stencil (identical to R16) ----
    const int r0 = xb * 4;
    const int nr = (HP - r0 < 4) ? (HP - r0) : 4;     // valid rows (4, or 1)
    const float* __restrict__ plane = g_csp + (size_t)b * CPLANE;

    for (int i4 = tid; i4 < 9 * CST4; i4 += NTHR) {
        int r  = i4 / CST4;
        int c4 = i4 - r * CST4;
        int pr = r0 + r;
        float4 v = make_float4(0.f, 0.f, 0.f, 0.f);
        if (pr < CROWS)
            v = *(reinterpret_cast<const float4*>(plane + (size_t)pr * CST) + c4);
        reinterpret_cast<float4*>(s_tile)[i4] = v;
    }
    __syncthreads();

    const float bias = __ldg(cb);
    float acc[4] = {bias, bias, bias, bias};
    float vx = bias;                          // extra col-256 pixel (tid>=252)
    float lsum = 0.f, lsq = 0.f;

    {
        const float* tb = s_tile + tid + 1;
#pragma unroll
        for (int c = 0; c < 6; ++c) {
            float t[9];
#pragma unroll
            for (int r = 0; r < 9; ++r) t[r] = tb[r * CST + c];
#pragma unroll
            for (int r = 0; r < 6; ++r) {
                float cf = s_c6[r * 6 + c];
#pragma unroll
                for (int k = 0; k < 4; ++k)
                    acc[k] = fmaf(cf, t[k + r], acc[k]);
            }
        }
#pragma unroll
        for (int k = 0; k < 4; ++k)
            if (k < nr) { lsum += acc[k]; lsq += acc[k] * acc[k]; }

        if (tid >= 252) {
            int k2 = tid - 252;
            if (k2 < nr) {
                const float* tb2 = s_tile + 257;
#pragma unroll
                for (int r = 0; r < 6; ++r)
#pragma unroll
                    for (int c = 0; c < 6; ++c)
                        vx = fmaf(s_c6[r * 6 + c], tb2[(k2 + r) * CST + c], vx);
                lsum += vx; lsq += vx * vx;
            }
        }
    }

    // Deterministic block reduction
#pragma unroll
    for (int o = 16; o > 0; o >>= 1) {
        lsum += __shfl_down_sync(0xffffffffu, lsum, o);
        lsq  += __shfl_down_sync(0xffffffffu, lsq,  o);
    }
    int wid = tid >> 5;
    if ((tid & 31) == 0) { s_red[wid][0] = lsum; s_red[wid][1] = lsq; }
    __syncthreads();
    if (tid == 0) {
        float a = 0.f, q = 0.f;
#pragma unroll
        for (int w = 0; w < 8; ++w) { a += s_red[w][0]; q += s_red[w][1]; }
        g_part[(b * NBLK + xb) * 2 + 0] = a;
        g_part[(b * NBLK + xb) * 2 + 1] = q;
    }

    img_barrier(tid, b);                      // image b's partials ready

    // ---- Phase C: redundant deterministic stats + normalize + LeakyReLU ----
    const float* __restrict__ part = g_part + b * NBLK * 2;
    float a = 0.f, q = 0.f;
#pragma unroll
    for (int i = 0; i < NBLK; ++i) {
        a += part[i * 2 + 0];
        q += part[i * 2 + 1];
    }
    const float inv_n = 1.0f / (float)NPIX;
    const float mean = a * inv_n;
    const float istd = rsqrtf(q * inv_n - mean * mean + LN_EPS);

    float* __restrict__ o = out + (size_t)b * NPIX;
#pragma unroll
    for (int k = 0; k < 4; ++k) {
        if (k < nr) {
            float v = (acc[k] - mean) * istd;
            o[(r0 + k) * WP + tid] = v >= 0.f ? v : NEG_SLOPE * v;
        }
    }
    if (tid >= 252) {
        int k2 = tid - 252;
        if (k2 < nr) {
            float v = (vx - mean) * istd;
            o[(r0 + k2) * WP + 256] = v >= 0.f ? v : NEG_SLOPE * v;
        }
    }
}

// ---------------------------------------------------------------------------

extern "C" void kernel_launch(void* const* d_in, const int* in_sizes, int n_in,
                              void* d_out, int out_size) {
    const float* x  = (const float*)d_in[0];   // [8,64,256,256]
    const float* cw = (const float*)d_in[1];   // [1,8]
    const float* cb = (const float*)d_in[2];   // [1]
    float* out = (float*)d_out;                // [8,1,257,257]
    (void)in_sizes; (void)n_in; (void)out_size;

    k_all<<<NGRID, NTHR>>>(x, cw, cb, out);
}